// round 5
// baseline (speedup 1.0000x reference)
#include <cuda_runtime.h>
#include <cuda_bf16.h>
#include <cstdint>

#define B_ 256
#define N_ 512
#define M_ 1024

#define SLOTS 3
#define WARPS_PER_BLOCK 4
#define THREADS (WARPS_PER_BLOCK * 32)
#define ROW_BYTES 4096                 // 1024 floats per row per warp
#define BLOCKS 592                     // 148 SMs * 4 CTAs

// Prescaled logits: logits * log2(e), computed by a preamble kernel each launch.
__device__ float g_lscaled[N_ * M_];

__global__ void prescale_logits_kernel(const float* __restrict__ logits) {
    int i = blockIdx.x * blockDim.x + threadIdx.x;
    if (i < N_ * M_) g_lscaled[i] = logits[i] * 1.4426950408889634f;
}

// Fast exp2: t in log2 domain. Magic-round (2^23+2^22) gives round(t) in the
// low mantissa bits; adding (bits<<23) to the poly's float bits is an exact
// ldexp because the low 9 bits of 0x4B400000 are zero.
// Degree-3 economized poly: output rel err ~3e-5 (threshold 1e-3).
__device__ __forceinline__ float exp2_fast(float t) {
    const float MAGIC = 12582912.0f;          // 2^23 + 2^22
    float tsh = t + MAGIC;
    int   bi  = __float_as_int(tsh);
    float f   = t - (tsh - MAGIC);            // f in [-0.5, 0.5]
    float p = fmaf(f, 0.05592078f, 0.24263103f);
    p = fmaf(f, p, 0.69312114f);
    p = fmaf(f, p, 0.99992486f);
    return __int_as_float(__float_as_int(p) + (bi << 23));
}

__device__ __forceinline__ void cp_async_16(uint32_t saddr, const void* gptr) {
    asm volatile("cp.async.cg.shared.global [%0], [%1], 16;"
                 :: "r"(saddr), "l"(gptr) : "memory");
}
__device__ __forceinline__ void cp_commit() {
    asm volatile("cp.async.commit_group;" ::: "memory");
}
__device__ __forceinline__ void cp_wait2() {
    asm volatile("cp.async.wait_group 2;" ::: "memory");
}

__global__ __launch_bounds__(THREADS, 4) void gsm_kernel(
    const float* __restrict__ x,      // [B, M]
    const float* __restrict__ gum,    // [B, N, M]
    float* __restrict__ out)          // [B, N]
{
    // 4 warps * 3 slots * 4KB = 48KB static shared (exactly the static limit)
    __shared__ __align__(16) char smem[WARPS_PER_BLOCK * SLOTS * ROW_BYTES];

    const int lane = threadIdx.x & 31;
    const int wIn  = threadIdx.x >> 5;
    char* wbase = smem + wIn * (SLOTS * ROW_BYTES);
    const uint32_t wbase_sa = (uint32_t)__cvta_generic_to_shared(wbase) + lane * 16;

    const int wg   = blockIdx.x * WARPS_PER_BLOCK + wIn;
    const int total_warps = BLOCKS * WARPS_PER_BLOCK;

    const int rows  = B_ * N_;
    const int chunk = (rows + total_warps - 1) / total_warps;
    const int row0  = wg * chunk;
    const int row1  = min(row0 + chunk, rows);
    if (row0 >= row1) return;

    const float L2E = 1.4426950408889634f;

    // ---- prologue: fill the 3-slot ring (clamp to last row; dups are harmless)
    #pragma unroll
    for (int s = 0; s < SLOTS; ++s) {
        int r = min(row0 + s, row1 - 1);
        const float4* g4 = (const float4*)(gum + (size_t)r * M_) + lane;
        uint32_t sa = wbase_sa + s * ROW_BYTES;
        #pragma unroll
        for (int i = 0; i < 8; ++i)
            cp_async_16(sa + i * 512, g4 + i * 32);
        cp_commit();
    }

    int slot = 0;
    for (int row = row0; row < row1; ++row) {
        cp_wait2();   // oldest of the 3 pending groups (= current slot) is done

        const int b = row >> 9;           // / N_
        const int n = row & (N_ - 1);     // % N_
        const float4* __restrict__ l4 = (const float4*)(g_lscaled + (size_t)n * M_) + lane;
        const float4* __restrict__ x4 = (const float4*)(x + (size_t)b * M_) + lane;
        const float4* sv = (const float4*)(wbase + slot * ROW_BYTES) + lane;

        float s = 0.0f, ws = 0.0f;
        #pragma unroll
        for (int i = 0; i < 8; ++i) {
            float4 gv = sv[i * 32];           // each lane reads bytes it copied itself
            float4 lv = __ldg(&l4[i * 32]);   // L2-resident (2 MB table)
            float4 xv = __ldg(&x4[i * 32]);   // L1-warm across the chunk

            float e0 = exp2_fast(fmaf(gv.x, L2E, lv.x));
            float e1 = exp2_fast(fmaf(gv.y, L2E, lv.y));
            float e2 = exp2_fast(fmaf(gv.z, L2E, lv.z));
            float e3 = exp2_fast(fmaf(gv.w, L2E, lv.w));

            s += e0; ws = fmaf(e0, xv.x, ws);
            s += e1; ws = fmaf(e1, xv.y, ws);
            s += e2; ws = fmaf(e2, xv.z, ws);
            s += e3; ws = fmaf(e3, xv.w, ws);
        }

        // refill this slot with row+SLOTS; ALWAYS commit (possibly-empty group)
        // so the wait_group<2> accounting stays exact through the tail.
        int nxt = row + SLOTS;
        if (nxt < row1) {
            const float4* g4 = (const float4*)(gum + (size_t)nxt * M_) + lane;
            uint32_t sa = wbase_sa + slot * ROW_BYTES;
            #pragma unroll
            for (int i = 0; i < 8; ++i)
                cp_async_16(sa + i * 512, g4 + i * 32);
        }
        cp_commit();

        // warp reduction
        #pragma unroll
        for (int o = 16; o > 0; o >>= 1) {
            s  += __shfl_xor_sync(0xFFFFFFFFu, s, o);
            ws += __shfl_xor_sync(0xFFFFFFFFu, ws, o);
        }
        if (lane == 0) out[row] = __fdividef(ws, s);

        slot = (slot == SLOTS - 1) ? 0 : slot + 1;
    }
}

extern "C" void kernel_launch(void* const* d_in, const int* in_sizes, int n_in,
                              void* d_out, int out_size) {
    // Identify inputs by element count (all three distinct):
    //   input  [B, M]    = 262144
    //   logits [N, M]    = 524288
    //   gumbel [B, N, M] = 134217728
    const float* x = nullptr;
    const float* logits = nullptr;
    const float* gum = nullptr;
    for (int i = 0; i < n_in; ++i) {
        if (in_sizes[i] == B_ * M_)       x      = (const float*)d_in[i];
        else if (in_sizes[i] == N_ * M_)  logits = (const float*)d_in[i];
        else                              gum    = (const float*)d_in[i];
    }

    prescale_logits_kernel<<<(N_ * M_ + 255) / 256, 256>>>(logits);

    gsm_kernel<<<BLOCKS, THREADS>>>(x, gum, (float*)d_out);
}

// round 6
// speedup vs baseline: 1.0832x; 1.0832x over previous
#include <cuda_runtime.h>
#include <cuda_bf16.h>

#define B_ 256
#define N_ 512
#define M_ 1024

// Prescaled logits: logits * log2(e), computed by a preamble kernel each launch.
__device__ float g_lscaled[N_ * M_];

__global__ void prescale_logits_kernel(const float* __restrict__ logits) {
    int i = blockIdx.x * blockDim.x + threadIdx.x;
    if (i < N_ * M_) g_lscaled[i] = logits[i] * 1.4426950408889634f;
}

// Fast exp2: t in log2 domain. Magic-round (2^23+2^22) gives round(t) in the
// low mantissa bits; adding (bits<<23) to the poly's float bits is an exact
// ldexp because the low 9 bits of 0x4B400000 are zero.
// Degree-3 economized poly: output rel err ~3e-5 (threshold 1e-3).
__device__ __forceinline__ float exp2_fast(float t) {
    const float MAGIC = 12582912.0f;          // 2^23 + 2^22
    float tsh = t + MAGIC;
    int   bi  = __float_as_int(tsh);
    float f   = t - (tsh - MAGIC);            // f in [-0.5, 0.5]
    float p = fmaf(f, 0.05592078f, 0.24263103f);
    p = fmaf(f, p, 0.69312114f);
    p = fmaf(f, p, 0.99992486f);
    return __int_as_float(__float_as_int(p) + (bi << 23));
}

__device__ __forceinline__ void prefetch_l2(const void* p) {
    asm volatile("prefetch.global.L2 [%0];" :: "l"(p));
}

__global__ __launch_bounds__(128, 8) void gsm_kernel(
    const float* __restrict__ x,      // [B, M]
    const float* __restrict__ gum,    // [B, N, M]
    float* __restrict__ out)          // [B, N]
{
    const int lane = threadIdx.x & 31;
    const int wg   = (blockIdx.x * blockDim.x + threadIdx.x) >> 5;
    const int total_warps = (gridDim.x * blockDim.x) >> 5;

    const int rows  = B_ * N_;
    const int chunk = (rows + total_warps - 1) / total_warps;
    const int row0  = wg * chunk;
    const int row1  = min(row0 + chunk, rows);
    if (row0 >= row1) return;

    const float L2E = 1.4426950408889634f;

    for (int row = row0; row < row1; ++row) {
        // One prefetch per lane covers the entire next row (32 lanes x 128B
        // lines = 4KB). No register, no scoreboard -> the DRAM stream runs
        // continuously ahead of demand; demand loads below become L2 hits.
        if (row + 1 < row1)
            prefetch_l2((const char*)(gum + (size_t)(row + 1) * M_) + lane * 128);

        const int b = row >> 9;           // / N_
        const int n = row & (N_ - 1);     // % N_

        const float4* __restrict__ g4 = (const float4*)(gum + (size_t)row * M_) + lane;
        const float4* __restrict__ l4 = (const float4*)(g_lscaled + (size_t)n * M_) + lane;
        const float4* __restrict__ x4 = (const float4*)(x + (size_t)b * M_) + lane;

        // Hoist the row's loads: 8 outstanding LDG.128 per warp.
        // Evict-first: the gumbel stream is single-use.
        float4 g[8];
        #pragma unroll
        for (int i = 0; i < 8; ++i) g[i] = __ldcs(&g4[i * 32]);

        float s = 0.0f, ws = 0.0f;
        #pragma unroll
        for (int i = 0; i < 8; ++i) {
            float4 lv = __ldg(&l4[i * 32]);   // L2-resident (2 MB table)
            float4 xv = __ldg(&x4[i * 32]);   // L1-warm across the chunk

            float e0 = exp2_fast(fmaf(g[i].x, L2E, lv.x));
            float e1 = exp2_fast(fmaf(g[i].y, L2E, lv.y));
            float e2 = exp2_fast(fmaf(g[i].z, L2E, lv.z));
            float e3 = exp2_fast(fmaf(g[i].w, L2E, lv.w));

            s += e0; ws = fmaf(e0, xv.x, ws);
            s += e1; ws = fmaf(e1, xv.y, ws);
            s += e2; ws = fmaf(e2, xv.z, ws);
            s += e3; ws = fmaf(e3, xv.w, ws);
        }

        // warp reduction (two independent shfl chains interleave)
        #pragma unroll
        for (int o = 16; o > 0; o >>= 1) {
            s  += __shfl_xor_sync(0xFFFFFFFFu, s, o);
            ws += __shfl_xor_sync(0xFFFFFFFFu, ws, o);
        }

        if (lane == 0) out[row] = __fdividef(ws, s);
    }
}

extern "C" void kernel_launch(void* const* d_in, const int* in_sizes, int n_in,
                              void* d_out, int out_size) {
    // Identify inputs by element count (all three distinct):
    //   input  [B, M]    = 262144
    //   logits [N, M]    = 524288
    //   gumbel [B, N, M] = 134217728
    const float* x = nullptr;
    const float* logits = nullptr;
    const float* gum = nullptr;
    for (int i = 0; i < n_in; ++i) {
        if (in_sizes[i] == B_ * M_)       x      = (const float*)d_in[i];
        else if (in_sizes[i] == N_ * M_)  logits = (const float*)d_in[i];
        else                              gum    = (const float*)d_in[i];
    }

    prescale_logits_kernel<<<(N_ * M_ + 255) / 256, 256>>>(logits);

    // Persistent single wave: 148 SMs x 8 CTAs x 128 threads = 4736 warps,
    // each owning a contiguous chunk of ~28 rows.
    gsm_kernel<<<1184, 128>>>(x, gum, (float*)d_out);
}

// round 7
// speedup vs baseline: 1.1883x; 1.0970x over previous
#include <cuda_runtime.h>
#include <cuda_bf16.h>

#define B_ 256
#define N_ 512
#define M_ 1024
#define WARPS_PER_BLOCK 4
#define BLOCKS 740                    // 148 SMs * 5 CTAs

// Fused e^z via exp2 with the log2e scale folded into the range reduction:
//   tsh = fma(z, L2E, MAGIC)   -> low mantissa bits hold round(z*log2e)
//   nrf = MAGIC - tsh          -> -round(z*log2e) as a float
//   f   = fma(z, L2E, nrf)     -> z*log2e - round(...), f in [-0.5, 0.5]
// Same op count as the prescaled-logits path; adding (bits<<23) to the poly's
// float bits is an exact ldexp because the low 9 bits of 0x4B400000 are zero.
// Degree-3 economized poly: output rel err ~3e-5 (threshold 1e-3).
__device__ __forceinline__ float exp_fast(float z) {
    const float L2E   = 1.4426950408889634f;
    const float MAGIC = 12582912.0f;          // 2^23 + 2^22
    float tsh = fmaf(z, L2E, MAGIC);
    float nrf = MAGIC - tsh;
    float f   = fmaf(z, L2E, nrf);
    int   bi  = __float_as_int(tsh);
    float p = fmaf(f, 0.05592078f, 0.24263103f);
    p = fmaf(f, p, 0.69312114f);
    p = fmaf(f, p, 0.99992486f);
    return __int_as_float(__float_as_int(p) + (bi << 23));
}

__device__ __forceinline__ void load_row(float4 g[8], const float* __restrict__ gum,
                                         int row, int lane) {
    const float4* __restrict__ g4 = (const float4*)(gum + (size_t)row * M_) + lane;
    #pragma unroll
    for (int i = 0; i < 8; ++i) g[i] = __ldcs(&g4[i * 32]);
}

__device__ __forceinline__ void compute_row(const float4 g[8],
                                            const float4* __restrict__ xs,  // smem, +lane
                                            const float* __restrict__ logits,
                                            float* __restrict__ out,
                                            int row, int lane) {
    const int n = row & (N_ - 1);     // % N_
    const float4* __restrict__ l4 = (const float4*)(logits + (size_t)n * M_) + lane;

    float s = 0.0f, ws = 0.0f;
    #pragma unroll
    for (int i = 0; i < 8; ++i) {
        float4 lv = __ldg(&l4[i * 32]);   // L2-resident (2 MB table)
        float4 xv = xs[i * 32];           // per-warp SMEM, each lane reads its own slot

        float e0 = exp_fast(g[i].x + lv.x);
        float e1 = exp_fast(g[i].y + lv.y);
        float e2 = exp_fast(g[i].z + lv.z);
        float e3 = exp_fast(g[i].w + lv.w);

        s += e0; ws = fmaf(e0, xv.x, ws);
        s += e1; ws = fmaf(e1, xv.y, ws);
        s += e2; ws = fmaf(e2, xv.z, ws);
        s += e3; ws = fmaf(e3, xv.w, ws);
    }

    #pragma unroll
    for (int o = 16; o > 0; o >>= 1) {
        s  += __shfl_xor_sync(0xFFFFFFFFu, s, o);
        ws += __shfl_xor_sync(0xFFFFFFFFu, ws, o);
    }
    if (lane == 0) out[row] = __fdividef(ws, s);
}

__global__ __launch_bounds__(128, 5) void gsm_kernel(
    const float* __restrict__ x,      // [B, M]
    const float* __restrict__ logits, // [N, M]
    const float* __restrict__ gum,    // [B, N, M]
    float* __restrict__ out)          // [B, N]
{
    // Per-warp x row cache: 4 warps * 1024 floats * 4B = 16 KB
    __shared__ float4 xs_s[WARPS_PER_BLOCK][M_ / 4];

    const int lane = threadIdx.x & 31;
    const int wIn  = threadIdx.x >> 5;
    const int wg   = blockIdx.x * WARPS_PER_BLOCK + wIn;
    const int total_warps = BLOCKS * WARPS_PER_BLOCK;

    const int rows  = B_ * N_;
    const int chunk = (rows + total_warps - 1) / total_warps;
    const int row0  = wg * chunk;
    const int row1  = min(row0 + chunk, rows);
    if (row0 >= row1) return;

    float4* xs = &xs_s[wIn][lane];    // lane-offset base; reads hit own slots only

    // Software pipeline (register double-buffer): row i+1's 8 LDG.128 are in
    // flight while row i computes -> ~8 DRAM loads outstanding continuously.
    float4 bufA[8], bufB[8];
    load_row(bufA, gum, row0, lane);

    int bcur = -1;
    int row = row0;
    for (;;) {
        {   // A live, prefetch into B
            int nxt = min(row + 1, row1 - 1);
            load_row(bufB, gum, nxt, lane);
            int b = row >> 9;
            if (b != bcur) {          // at most twice per chunk (chunk=45 < 512)
                const float4* x4 = (const float4*)(x + (size_t)b * M_) + lane;
                #pragma unroll
                for (int i = 0; i < 8; ++i) xs[i * 32] = __ldg(&x4[i * 32]);
                bcur = b;
            }
            compute_row(bufA, xs, logits, out, row, lane);
            if (++row >= row1) break;
        }
        {   // B live, prefetch into A
            int nxt = min(row + 1, row1 - 1);
            load_row(bufA, gum, nxt, lane);
            int b = row >> 9;
            if (b != bcur) {
                const float4* x4 = (const float4*)(x + (size_t)b * M_) + lane;
                #pragma unroll
                for (int i = 0; i < 8; ++i) xs[i * 32] = __ldg(&x4[i * 32]);
                bcur = b;
            }
            compute_row(bufB, xs, logits, out, row, lane);
            if (++row >= row1) break;
        }
    }
}

extern "C" void kernel_launch(void* const* d_in, const int* in_sizes, int n_in,
                              void* d_out, int out_size) {
    // Identify inputs by element count (all three distinct):
    //   input  [B, M]    = 262144
    //   logits [N, M]    = 524288
    //   gumbel [B, N, M] = 134217728
    const float* x = nullptr;
    const float* logits = nullptr;
    const float* gum = nullptr;
    for (int i = 0; i < n_in; ++i) {
        if (in_sizes[i] == B_ * M_)       x      = (const float*)d_in[i];
        else if (in_sizes[i] == N_ * M_)  logits = (const float*)d_in[i];
        else                              gum    = (const float*)d_in[i];
    }

    // Single launch: prescale folded into exp_fast's range reduction.
    gsm_kernel<<<BLOCKS, 128>>>(x, logits, gum, (float*)d_out);
}